// round 9
// baseline (speedup 1.0000x reference)
#include <cuda_runtime.h>
#include <cuda_bf16.h>
#include <math.h>

// AdaptiveGraphGenerator: dim=128, B=1, N=1024.
// edge predictor is dead code (edge_probs = ones). adj = (1.0 > threshold).
// Real work: node encoder LN(x@W1+b1) -> GELU -> @W2+b2.
//
// R9: ROWS=8 x 1024 threads x 128 blocks (single wave, 1 block/SM, 32 warps/SM).
// GEMM loops: thread = (col-group, k-slice, row-pair); 8 FFMA per LDG.128,
// x/gelu via LDS.128. k-partials combined through 32KB shared scratch.
// Per-block fixed costs amortized over 8 rows.

#define DIM 128
#define HID 256
#define NROWS 1024
#define ROWS 8
#define THREADS 1024
#define NBLOCKS (NROWS / ROWS)   // 128

__device__ __forceinline__ float gelu_exact(float v) {
    return 0.5f * v * (1.0f + erff(v * 0.70710678118654752f));
}

__global__ __launch_bounds__(THREADS, 1)
void fused_kernel(const float* __restrict__ x,
                  const float* __restrict__ W1,
                  const float* __restrict__ b1,
                  const float* __restrict__ ln_g,
                  const float* __restrict__ ln_b,
                  const float* __restrict__ W2,
                  const float* __restrict__ b2,
                  const float* __restrict__ thr,
                  float* __restrict__ adj_out,
                  float* __restrict__ node_out) {
    __shared__ float sx[ROWS][DIM];        // 4 KB
    __shared__ float sh[ROWS][HID];        // 8 KB  gelu(h)
    __shared__ float scratch[8192];        // 32 KB: p1[4][8][256] then p2[8][8][128]
    __shared__ float s_sum[32][2];
    __shared__ float s_sq[32][2];

    const int tid  = threadIdx.x;           // 0..1023
    const int row0 = blockIdx.x * ROWS;

    // ---- early scalar prefetches (latency hidden under GEMM1) ----
    const float tv    = __ldg(&thr[0]);
    const float bias1 = __ldg(&b1[tid & 255]);
    const float gg    = __ldg(&ln_g[tid & 255]);
    const float bb    = __ldg(&ln_b[tid & 255]);
    const float bias2 = __ldg(&b2[tid & (DIM - 1)]);

    // ---- load x tile [8,128] (thread t -> r=t>>7, c=t&127) ----
    {
        const int r = tid >> 7;
        const int c = tid & (DIM - 1);
        sx[r][c] = __ldg(&x[(size_t)(row0 + r) * DIM + c]);
    }

    // ---- adj fill: this block's 8192-float slice (2048 float4) ----
    {
        const float v = (1.0f > tv) ? 1.0f : 0.0f;
        const float4 f4 = make_float4(v, v, v, v);
        float4* a4 = reinterpret_cast<float4*>(adj_out) + (size_t)blockIdx.x * 2048;
        a4[tid]        = f4;
        a4[tid + 1024] = f4;
    }
    __syncthreads();

    // ---- GEMM1: cg = tid&63 -> cols 4cg..4cg+3; hh = (tid>>6)&3 -> k slice
    //      [32hh,32hh+32); rp = tid>>8 -> rows {2rp, 2rp+1}. ----
    {
        const int cg = tid & 63;
        const int hh = (tid >> 6) & 3;
        const int rp = tid >> 8;            // 0..3
        const int r0 = 2 * rp, r1 = 2 * rp + 1;
        const float* w1p = W1 + (size_t)(hh * 32) * HID + 4 * cg;
        float4 a0 = make_float4(0.f, 0.f, 0.f, 0.f);
        float4 a1 = a0;
        #pragma unroll
        for (int kb = 0; kb < 32; kb += 4) {
            const float4 xv0 = *reinterpret_cast<const float4*>(&sx[r0][hh * 32 + kb]);
            const float4 xv1 = *reinterpret_cast<const float4*>(&sx[r1][hh * 32 + kb]);
            const float* xs0 = reinterpret_cast<const float*>(&xv0);
            const float* xs1 = reinterpret_cast<const float*>(&xv1);
            #pragma unroll
            for (int u = 0; u < 4; u++) {
                const float4 w4 =
                    *reinterpret_cast<const float4*>(w1p + (size_t)(kb + u) * HID);
                const float x0 = xs0[u];
                const float x1 = xs1[u];
                a0.x = fmaf(x0, w4.x, a0.x); a0.y = fmaf(x0, w4.y, a0.y);
                a0.z = fmaf(x0, w4.z, a0.z); a0.w = fmaf(x0, w4.w, a0.w);
                a1.x = fmaf(x1, w4.x, a1.x); a1.y = fmaf(x1, w4.y, a1.y);
                a1.z = fmaf(x1, w4.z, a1.z); a1.w = fmaf(x1, w4.w, a1.w);
            }
        }
        // p1[hh][r][c] = scratch[(hh*8+r)*256 + c]; STS.128 conflict-free
        float4* sc = reinterpret_cast<float4*>(scratch);
        sc[((hh * 8 + r0) * 256 + 4 * cg) >> 2] = a0;
        sc[((hh * 8 + r1) * 256 + 4 * cg) >> 2] = a1;
    }
    __syncthreads();

    // ---- combine k-partials + LN stats.
    //      thread t: c = t&255, rq = t>>8 -> rows {2rq, 2rq+1}. ----
    float v0, v1;
    const int rq = tid >> 8;                // 0..3
    {
        const int c  = tid & 255;
        const int r0 = 2 * rq, r1 = 2 * rq + 1;
        v0 = bias1; v1 = bias1;
        #pragma unroll
        for (int hh = 0; hh < 4; hh++) {
            v0 += scratch[(hh * 8 + r0) * 256 + c];
            v1 += scratch[(hh * 8 + r1) * 256 + c];
        }
        const int wid  = tid >> 5;          // 0..31
        const int lane = tid & 31;
        float s0 = v0, q0 = v0 * v0, s1 = v1, q1 = v1 * v1;
        #pragma unroll
        for (int o = 16; o > 0; o >>= 1) {
            s0 += __shfl_xor_sync(0xffffffffu, s0, o);
            q0 += __shfl_xor_sync(0xffffffffu, q0, o);
            s1 += __shfl_xor_sync(0xffffffffu, s1, o);
            q1 += __shfl_xor_sync(0xffffffffu, q1, o);
        }
        if (lane == 0) {
            s_sum[wid][0] = s0; s_sq[wid][0] = q0;
            s_sum[wid][1] = s1; s_sq[wid][1] = q1;
        }
    }
    __syncthreads();

    // ---- per-thread LN finalize + GELU -> sh (rows 2rq, 2rq+1) ----
    {
        const int c  = tid & 255;
        const int w0 = 8 * rq;              // this row-pair's 8 partial warps
        float s0 = 0.f, q0 = 0.f, s1 = 0.f, q1 = 0.f;
        #pragma unroll
        for (int w = 0; w < 8; w++) {
            s0 += s_sum[w0 + w][0]; q0 += s_sq[w0 + w][0];
            s1 += s_sum[w0 + w][1]; q1 += s_sq[w0 + w][1];
        }
        const float m0 = s0 * (1.0f / HID);
        const float m1 = s1 * (1.0f / HID);
        const float rs0 = rsqrtf(q0 * (1.0f / HID) - m0 * m0 + 1e-5f);
        const float rs1 = rsqrtf(q1 * (1.0f / HID) - m1 * m1 + 1e-5f);
        sh[2 * rq + 0][c] = gelu_exact((v0 - m0) * rs0 * gg + bb);
        sh[2 * rq + 1][c] = gelu_exact((v1 - m1) * rs1 * gg + bb);
    }
    __syncthreads();

    // ---- GEMM2: cg2 = tid&31 -> cols 4cg2..+3; h2 = (tid>>5)&7 -> k slice
    //      [32h2,32h2+32); rp2 = tid>>8 -> rows {2rp2, 2rp2+1}.
    //      scratch reuse safe: last read before the LN-partial barrier. ----
    {
        const int cg2 = tid & 31;
        const int h2  = (tid >> 5) & 7;
        const int rp2 = tid >> 8;           // 0..3
        const int r0 = 2 * rp2, r1 = 2 * rp2 + 1;
        const float* w2p = W2 + (size_t)(h2 * 32) * DIM + 4 * cg2;
        float4 a0 = make_float4(0.f, 0.f, 0.f, 0.f);
        float4 a1 = a0;
        #pragma unroll
        for (int kb = 0; kb < 32; kb += 4) {
            const float4 gv0 = *reinterpret_cast<const float4*>(&sh[r0][h2 * 32 + kb]);
            const float4 gv1 = *reinterpret_cast<const float4*>(&sh[r1][h2 * 32 + kb]);
            const float* gs0 = reinterpret_cast<const float*>(&gv0);
            const float* gs1 = reinterpret_cast<const float*>(&gv1);
            #pragma unroll
            for (int u = 0; u < 4; u++) {
                const float4 w4 =
                    *reinterpret_cast<const float4*>(w2p + (size_t)(kb + u) * DIM);
                const float g0 = gs0[u];
                const float g1 = gs1[u];
                a0.x = fmaf(g0, w4.x, a0.x); a0.y = fmaf(g0, w4.y, a0.y);
                a0.z = fmaf(g0, w4.z, a0.z); a0.w = fmaf(g0, w4.w, a0.w);
                a1.x = fmaf(g1, w4.x, a1.x); a1.y = fmaf(g1, w4.y, a1.y);
                a1.z = fmaf(g1, w4.z, a1.z); a1.w = fmaf(g1, w4.w, a1.w);
            }
        }
        // p2[h2][r][c] = scratch[(h2*8+r)*128 + c]; STS.128 conflict-free
        float4* sc = reinterpret_cast<float4*>(scratch);
        sc[((h2 * 8 + r0) * 128 + 4 * cg2) >> 2] = a0;
        sc[((h2 * 8 + r1) * 128 + 4 * cg2) >> 2] = a1;
    }
    __syncthreads();

    // ---- combine GEMM2 k-partials + store (thread t -> r=t>>7, c=t&127) ----
    {
        const int r = tid >> 7;             // 0..7
        const int c = tid & (DIM - 1);
        float o = bias2;
        #pragma unroll
        for (int h2 = 0; h2 < 8; h2++)
            o += scratch[(h2 * 8 + r) * 128 + c];
        node_out[(size_t)(row0 + r) * DIM + c] = o;
    }
}

extern "C" void kernel_launch(void* const* d_in, const int* in_sizes, int n_in,
                              void* d_out, int out_size) {
    const float* x    = (const float*)d_in[0];
    const float* W1   = (const float*)d_in[1];
    const float* b1   = (const float*)d_in[2];
    const float* ln_g = (const float*)d_in[3];
    const float* ln_b = (const float*)d_in[4];
    const float* W2   = (const float*)d_in[5];
    const float* b2   = (const float*)d_in[6];
    const float* thr  = (const float*)d_in[11];

    float* out = (float*)d_out;
    float* adj_out  = out;                      // [1,1024,1024,1]
    float* node_out = out + NROWS * NROWS;      // [1,1024,128]

    fused_kernel<<<NBLOCKS, THREADS>>>(x, W1, b1, ln_g, ln_b, W2, b2, thr,
                                       adj_out, node_out);
}